// round 3
// baseline (speedup 1.0000x reference)
#include <cuda_runtime.h>
#include <cuda_fp16.h>
#include <cuda_bf16.h>

#define NN    50000
#define INDIM 128
#define HEADS 8
#define RDIM  16
#define DDIM  16

// Scratch (no cudaMalloc allowed): K, Q, V projections (fp16) + z accumulator
__device__ __half g_K[NN * 128];
__device__ __half g_Q[NN * 128];
__device__ __half g_V[NN * 128];
__device__ float  g_z[NN * HEADS];

// ---------------------------------------------------------------------------
// Zero-init d_out (wV accumulator) and g_z
// ---------------------------------------------------------------------------
__global__ void zero_kernel(float4* __restrict__ out) {
    int i = blockIdx.x * blockDim.x + threadIdx.x;
    if (i < NN * 32) out[i] = make_float4(0.f, 0.f, 0.f, 0.f);
    if (i < NN * 2)  ((float4*)g_z)[i] = make_float4(0.f, 0.f, 0.f, 0.f);
}

// ---------------------------------------------------------------------------
// Fused K/Q/V projection GEMM: C = h @ W, one weight matrix per blockIdx.y
// BM=128, BN=128 (full weight width), BK=8, 256 threads, 8x8 per-thread tile.
// Epilogue converts to fp16.
// ---------------------------------------------------------------------------
__global__ __launch_bounds__(256, 2)
void kqv_gemm(const float* __restrict__ h,
              const float* __restrict__ wq,   // K = h @ q
              const float* __restrict__ wp,   // Q = h @ p
              const float* __restrict__ wv) { // V = h @ Wv
    __shared__ float as[8][128];   // A^T tile: as[k][m]
    __shared__ float bs[8][128];   // B tile:   bs[k][n]

    const float* w;
    __half* outp;
    if (blockIdx.y == 0)      { w = wq; outp = g_K; }
    else if (blockIdx.y == 1) { w = wp; outp = g_Q; }
    else                      { w = wv; outp = g_V; }

    const int m0  = blockIdx.x * 128;
    const int tid = threadIdx.x;
    const int ty  = tid >> 4;    // 0..15 -> m group
    const int tx  = tid & 15;    // 0..15 -> n group

    // A-load mapping: 128 rows x 8 k per tile
    const int lm = tid >> 1;          // row within tile 0..127
    const int lk = (tid & 1) * 4;     // k offset 0 or 4
    // B-load mapping: 8 k-rows x 128 n
    const int bk = tid >> 5;          // 0..7
    const int bn = (tid & 31) * 4;    // 0..124

    float acc[8][8];
#pragma unroll
    for (int i = 0; i < 8; i++)
#pragma unroll
        for (int j = 0; j < 8; j++) acc[i][j] = 0.f;

    for (int k0 = 0; k0 < 128; k0 += 8) {
        float4 av = make_float4(0.f, 0.f, 0.f, 0.f);
        int row = m0 + lm;
        if (row < NN) av = *(const float4*)&h[row * 128 + k0 + lk];
        as[lk + 0][lm] = av.x;
        as[lk + 1][lm] = av.y;
        as[lk + 2][lm] = av.z;
        as[lk + 3][lm] = av.w;
        *(float4*)&bs[bk][bn] = *(const float4*)&w[(k0 + bk) * 128 + bn];
        __syncthreads();

#pragma unroll
        for (int k = 0; k < 8; k++) {
            float a[8], b[8];
            *(float4*)(a)     = *(const float4*)&as[k][ty * 8];
            *(float4*)(a + 4) = *(const float4*)&as[k][ty * 8 + 4];
            *(float4*)(b)     = *(const float4*)&bs[k][tx * 8];
            *(float4*)(b + 4) = *(const float4*)&bs[k][tx * 8 + 4];
#pragma unroll
            for (int i = 0; i < 8; i++)
#pragma unroll
                for (int j = 0; j < 8; j++)
                    acc[i][j] = fmaf(a[i], b[j], acc[i][j]);
        }
        __syncthreads();
    }

#pragma unroll
    for (int i = 0; i < 8; i++) {
        int row = m0 + ty * 8 + i;
        if (row < NN) {
            __half2 h0 = __floats2half2_rn(acc[i][0], acc[i][1]);
            __half2 h1 = __floats2half2_rn(acc[i][2], acc[i][3]);
            __half2 h2 = __floats2half2_rn(acc[i][4], acc[i][5]);
            __half2 h3 = __floats2half2_rn(acc[i][6], acc[i][7]);
            uint4 pack;
            pack.x = *(unsigned*)&h0;
            pack.y = *(unsigned*)&h1;
            pack.z = *(unsigned*)&h2;
            pack.w = *(unsigned*)&h3;
            *(uint4*)&outp[row * 128 + tx * 8] = pack;
        }
    }
}

// ---------------------------------------------------------------------------
// Edge kernel: one warp per edge (grid-stride).
// lane t: head = t>>2, covers channels [4t, 4t+4) of the 128-wide node row.
// Each lane loads 4 halves (8B, uint2) per gather -> 256B coalesced per row.
// ---------------------------------------------------------------------------
__global__ void edge_kernel(const int* __restrict__ src,
                            const int* __restrict__ dst,
                            float* __restrict__ out,
                            int E) {
    const int lane    = threadIdx.x & 31;
    const int warpId  = (blockIdx.x * blockDim.x + threadIdx.x) >> 5;
    const int nwarps  = (gridDim.x * blockDim.x) >> 5;
    const uint2* __restrict__ K2 = (const uint2*)g_K;
    const uint2* __restrict__ Q2 = (const uint2*)g_Q;
    const uint2* __restrict__ V2 = (const uint2*)g_V;
    const int head = lane >> 2;

    for (int e = warpId; e < E; e += nwarps) {
        const int s = __ldg(&src[e]);
        const int d = __ldg(&dst[e]);

        uint2 kr = K2[s * 32 + lane];
        uint2 qr = Q2[d * 32 + lane];
        float2 k0 = __half22float2(*(__half2*)&kr.x);
        float2 k1 = __half22float2(*(__half2*)&kr.y);
        float2 q0 = __half22float2(*(__half2*)&qr.x);
        float2 q1 = __half22float2(*(__half2*)&qr.y);
        float ps = k0.x * q0.x + k0.y * q0.y + k1.x * q1.x + k1.y * q1.y;
        ps += __shfl_xor_sync(0xFFFFFFFFu, ps, 1);
        ps += __shfl_xor_sync(0xFFFFFFFFu, ps, 2);
        // score = exp(clip(dot / 4, -5, 5))
        float sc = __expf(fminf(fmaxf(ps * 0.25f, -5.f), 5.f));

        uint2 vr = V2[s * 32 + lane];
        float2 v0 = __half22float2(*(__half2*)&vr.x);
        float2 v1 = __half22float2(*(__half2*)&vr.y);
        float rx = v0.x * sc, ry = v0.y * sc, rz = v1.x * sc, rw = v1.y * sc;
        float* addr = out + d * 128 + lane * 4;
        asm volatile("red.global.add.v4.f32 [%0], {%1, %2, %3, %4};"
                     :: "l"(addr), "f"(rx), "f"(ry), "f"(rz), "f"(rw)
                     : "memory");
        if ((lane & 3) == 0) atomicAdd(&g_z[d * HEADS + head], sc);
    }
}

// ---------------------------------------------------------------------------
// Finalize: out = wV / z, z==0 -> 0.001
// ---------------------------------------------------------------------------
__global__ void finalize_kernel(float4* __restrict__ out) {
    int i = blockIdx.x * blockDim.x + threadIdx.x;   // over NN*32 float4s
    if (i < NN * 32) {
        int n    = i >> 5;
        int head = (i >> 2) & 7;
        float zz = g_z[n * HEADS + head];
        zz = (zz == 0.f) ? 0.001f : zz;
        float inv = 1.0f / zz;
        float4 v = out[i];
        v.x *= inv; v.y *= inv; v.z *= inv; v.w *= inv;
        out[i] = v;
    }
}

extern "C" void kernel_launch(void* const* d_in, const int* in_sizes, int n_in,
                              void* d_out, int out_size) {
    const float* h   = (const float*)d_in[0];
    const int*   src = (const int*)d_in[1];
    const int*   dst = (const int*)d_in[2];
    const float* p   = (const float*)d_in[3];
    const float* q   = (const float*)d_in[4];
    const float* wv  = (const float*)d_in[5];
    float* out = (float*)d_out;
    const int E = in_sizes[1];

    zero_kernel<<<(NN * 32 + 255) / 256, 256>>>((float4*)out);

    dim3 ggrid((NN + 127) / 128, 3);
    kqv_gemm<<<ggrid, 256>>>(h, q, p, wv);

    edge_kernel<<<4096, 256>>>(src, dst, out, E);

    finalize_kernel<<<(NN * 32 + 255) / 256, 256>>>((float4*)out);
}

// round 4
// speedup vs baseline: 2.0602x; 2.0602x over previous
#include <cuda_runtime.h>
#include <cuda_fp16.h>
#include <cuda_bf16.h>

#define NN    50000
#define EMAX  1700000
#define HEADS 8

// Scratch (no cudaMalloc allowed)
__device__ __half g_K[NN * 128];
__device__ __half g_Q[NN * 128];
__device__ __half g_V[NN * 128];
__device__ int    g_count[NN];
__device__ int    g_rowstart[NN + 1];
__device__ int    g_cursor[NN];
__device__ int    g_bsum[256];
__device__ int    g_sorted_src[EMAX];

#define SCAN_BLOCKS 196   // 196*256 = 50176 >= NN

// ---------------------------------------------------------------------------
// Zero histogram counters
// ---------------------------------------------------------------------------
__global__ void init_kernel() {
    int i = blockIdx.x * blockDim.x + threadIdx.x;
    if (i < NN) g_count[i] = 0;
}

// ---------------------------------------------------------------------------
// Fused K/Q/V projection GEMM: C = h @ W, one weight matrix per blockIdx.y
// BM=128, BN=128, BK=8, 256 threads, 8x8 per-thread tile. fp16 epilogue.
// ---------------------------------------------------------------------------
__global__ __launch_bounds__(256, 2)
void kqv_gemm(const float* __restrict__ h,
              const float* __restrict__ wq,
              const float* __restrict__ wp,
              const float* __restrict__ wv) {
    __shared__ float as[8][128];
    __shared__ float bs[8][128];

    const float* w;
    __half* outp;
    if (blockIdx.y == 0)      { w = wq; outp = g_K; }
    else if (blockIdx.y == 1) { w = wp; outp = g_Q; }
    else                      { w = wv; outp = g_V; }

    const int m0  = blockIdx.x * 128;
    const int tid = threadIdx.x;
    const int ty  = tid >> 4;
    const int tx  = tid & 15;
    const int lm = tid >> 1;
    const int lk = (tid & 1) * 4;
    const int bk = tid >> 5;
    const int bn = (tid & 31) * 4;

    float acc[8][8];
#pragma unroll
    for (int i = 0; i < 8; i++)
#pragma unroll
        for (int j = 0; j < 8; j++) acc[i][j] = 0.f;

    for (int k0 = 0; k0 < 128; k0 += 8) {
        float4 av = make_float4(0.f, 0.f, 0.f, 0.f);
        int row = m0 + lm;
        if (row < NN) av = *(const float4*)&h[row * 128 + k0 + lk];
        as[lk + 0][lm] = av.x;
        as[lk + 1][lm] = av.y;
        as[lk + 2][lm] = av.z;
        as[lk + 3][lm] = av.w;
        *(float4*)&bs[bk][bn] = *(const float4*)&w[(k0 + bk) * 128 + bn];
        __syncthreads();

#pragma unroll
        for (int k = 0; k < 8; k++) {
            float a[8], b[8];
            *(float4*)(a)     = *(const float4*)&as[k][ty * 8];
            *(float4*)(a + 4) = *(const float4*)&as[k][ty * 8 + 4];
            *(float4*)(b)     = *(const float4*)&bs[k][tx * 8];
            *(float4*)(b + 4) = *(const float4*)&bs[k][tx * 8 + 4];
#pragma unroll
            for (int i = 0; i < 8; i++)
#pragma unroll
                for (int j = 0; j < 8; j++)
                    acc[i][j] = fmaf(a[i], b[j], acc[i][j]);
        }
        __syncthreads();
    }

#pragma unroll
    for (int i = 0; i < 8; i++) {
        int row = m0 + ty * 8 + i;
        if (row < NN) {
            __half2 h0 = __floats2half2_rn(acc[i][0], acc[i][1]);
            __half2 h1 = __floats2half2_rn(acc[i][2], acc[i][3]);
            __half2 h2 = __floats2half2_rn(acc[i][4], acc[i][5]);
            __half2 h3 = __floats2half2_rn(acc[i][6], acc[i][7]);
            uint4 pack;
            pack.x = *(unsigned*)&h0;
            pack.y = *(unsigned*)&h1;
            pack.z = *(unsigned*)&h2;
            pack.w = *(unsigned*)&h3;
            *(uint4*)&outp[row * 128 + tx * 8] = pack;
        }
    }
}

// ---------------------------------------------------------------------------
// Counting sort by dst: histogram -> 2-level exclusive scan -> scatter
// ---------------------------------------------------------------------------
__global__ void hist_kernel(const int* __restrict__ dst, int E) {
    int e = blockIdx.x * blockDim.x + threadIdx.x;
    if (e < E) atomicAdd(&g_count[dst[e]], 1);
}

__global__ void scan1_kernel() {   // SCAN_BLOCKS x 256
    __shared__ int sh[256];
    int i = blockIdx.x * 256 + threadIdx.x;
    int v = (i < NN) ? g_count[i] : 0;
    sh[threadIdx.x] = v;
    __syncthreads();
#pragma unroll
    for (int off = 1; off < 256; off <<= 1) {
        int t = (threadIdx.x >= off) ? sh[threadIdx.x - off] : 0;
        __syncthreads();
        sh[threadIdx.x] += t;
        __syncthreads();
    }
    if (i < NN) g_rowstart[i] = sh[threadIdx.x] - v;   // exclusive
    if (threadIdx.x == 255) g_bsum[blockIdx.x] = sh[255];
}

__global__ void scan2_kernel() {   // 1 x 256
    __shared__ int sh[256];
    int v = (threadIdx.x < SCAN_BLOCKS) ? g_bsum[threadIdx.x] : 0;
    sh[threadIdx.x] = v;
    __syncthreads();
#pragma unroll
    for (int off = 1; off < 256; off <<= 1) {
        int t = (threadIdx.x >= off) ? sh[threadIdx.x - off] : 0;
        __syncthreads();
        sh[threadIdx.x] += t;
        __syncthreads();
    }
    if (threadIdx.x < SCAN_BLOCKS) g_bsum[threadIdx.x] = sh[threadIdx.x] - v;
}

__global__ void scan3_kernel(int E) {   // SCAN_BLOCKS x 256
    int i = blockIdx.x * 256 + threadIdx.x;
    if (i < NN) {
        int r = g_rowstart[i] + g_bsum[blockIdx.x];
        g_rowstart[i] = r;
        g_cursor[i]   = r;
    }
    if (i == 0) g_rowstart[NN] = E;
}

__global__ void scatter_kernel(const int* __restrict__ src,
                               const int* __restrict__ dst, int E) {
    int e = blockIdx.x * blockDim.x + threadIdx.x;
    if (e < E) {
        int pos = atomicAdd(&g_cursor[dst[e]], 1);
        g_sorted_src[pos] = src[e];
    }
}

// ---------------------------------------------------------------------------
// Node kernel: one warp per dst node. Q[d] kept in registers; loop over
// in-edges gathering K[src], V[src] (fp16); fp32 register accumulation of
// wV and z; fused finalize write out = wV / max(z, eps-path).
// lane t: head = t>>2, channels [4t, 4t+4).
// ---------------------------------------------------------------------------
__global__ __launch_bounds__(256)
void node_kernel(float* __restrict__ out) {
    const int lane = threadIdx.x & 31;
    const int d    = (blockIdx.x * blockDim.x + threadIdx.x) >> 5;
    if (d >= NN) return;

    const uint2* __restrict__ K2 = (const uint2*)g_K;
    const uint2* __restrict__ Q2 = (const uint2*)g_Q;
    const uint2* __restrict__ V2 = (const uint2*)g_V;

    // Q[d] for this lane's 4 channels
    uint2 qr = Q2[d * 32 + lane];
    float2 q0 = __half22float2(*(__half2*)&qr.x);
    float2 q1 = __half22float2(*(__half2*)&qr.y);

    const int beg = g_rowstart[d];
    const int end = g_rowstart[d + 1];

    float a0 = 0.f, a1 = 0.f, a2 = 0.f, a3 = 0.f, z = 0.f;

    int s = (beg < end) ? g_sorted_src[beg] : 0;
    for (int i = beg; i < end; i++) {
        int s_next = (i + 1 < end) ? g_sorted_src[i + 1] : 0;

        uint2 kr = K2[s * 32 + lane];
        uint2 vr = V2[s * 32 + lane];

        float2 k0 = __half22float2(*(__half2*)&kr.x);
        float2 k1 = __half22float2(*(__half2*)&kr.y);
        float ps = k0.x * q0.x + k0.y * q0.y + k1.x * q1.x + k1.y * q1.y;
        ps += __shfl_xor_sync(0xFFFFFFFFu, ps, 1);
        ps += __shfl_xor_sync(0xFFFFFFFFu, ps, 2);
        float sc = __expf(fminf(fmaxf(ps * 0.25f, -5.f), 5.f));

        float2 v0 = __half22float2(*(__half2*)&vr.x);
        float2 v1 = __half22float2(*(__half2*)&vr.y);
        a0 = fmaf(v0.x, sc, a0);
        a1 = fmaf(v0.y, sc, a1);
        a2 = fmaf(v1.x, sc, a2);
        a3 = fmaf(v1.y, sc, a3);
        z += sc;

        s = s_next;
    }

    float zz = (z == 0.f) ? 0.001f : z;
    float inv = 1.0f / zz;
    float4 r = make_float4(a0 * inv, a1 * inv, a2 * inv, a3 * inv);
    *(float4*)&out[d * 128 + lane * 4] = r;
}

extern "C" void kernel_launch(void* const* d_in, const int* in_sizes, int n_in,
                              void* d_out, int out_size) {
    const float* h   = (const float*)d_in[0];
    const int*   src = (const int*)d_in[1];
    const int*   dst = (const int*)d_in[2];
    const float* p   = (const float*)d_in[3];
    const float* q   = (const float*)d_in[4];
    const float* wv  = (const float*)d_in[5];
    float* out = (float*)d_out;
    const int E = in_sizes[1];
    const int eg = (E + 255) / 256;

    init_kernel<<<SCAN_BLOCKS, 256>>>();

    dim3 ggrid((NN + 127) / 128, 3);
    kqv_gemm<<<ggrid, 256>>>(h, q, p, wv);

    hist_kernel<<<eg, 256>>>(dst, E);
    scan1_kernel<<<SCAN_BLOCKS, 256>>>();
    scan2_kernel<<<1, 256>>>();
    scan3_kernel<<<SCAN_BLOCKS, 256>>>(E);
    scatter_kernel<<<eg, 256>>>(src, dst, E);

    node_kernel<<<(NN * 32 + 255) / 256, 256>>>(out);
}

// round 7
// speedup vs baseline: 2.9857x; 1.4493x over previous
#include <cuda_runtime.h>
#include <cuda_fp16.h>
#include <cuda_bf16.h>
#include <mma.h>
#include <cstdint>

using namespace nvcuda;

#define NN    50000
#define EMAX  1700000
#define HEADS 8

// Scratch (no cudaMalloc allowed)
__device__ __half g_K[NN * 128];
__device__ __half g_Q[NN * 128];
__device__ __half g_V[NN * 128];
__device__ __half g_hh[NN * 128];          // h in fp16
__device__ __half g_wh[3 * 128 * 128];     // q, p, Wv in fp16
__device__ int    g_count[NN];
__device__ int    g_rowstart[NN + 1];
__device__ int    g_cursor[NN];
__device__ int    g_bsum[256];
__device__ int    g_sorted_src[EMAX];

#define SCAN_BLOCKS 196   // 196*256 = 50176 >= NN

// ---------------------------------------------------------------------------
// Zero histogram counters
// ---------------------------------------------------------------------------
__global__ void init_kernel() {
    int i = blockIdx.x * blockDim.x + threadIdx.x;
    if (i < NN) g_count[i] = 0;
}

// ---------------------------------------------------------------------------
// fp32 -> fp16 conversions
// ---------------------------------------------------------------------------
__global__ void convh_kernel(const float4* __restrict__ h) {
    int i = blockIdx.x * blockDim.x + threadIdx.x;   // over NN*32 float4s
    if (i < NN * 32) {
        float4 v = h[i];
        __half2 h0 = __floats2half2_rn(v.x, v.y);
        __half2 h1 = __floats2half2_rn(v.z, v.w);
        uint2 pk;
        pk.x = *(unsigned*)&h0;
        pk.y = *(unsigned*)&h1;
        ((uint2*)g_hh)[i] = pk;
    }
}

__global__ void convw_kernel(const float4* __restrict__ wq,
                             const float4* __restrict__ wp,
                             const float4* __restrict__ wv) {
    int i = blockIdx.x * blockDim.x + threadIdx.x;   // 3*4096 float4s
    if (i < 3 * 4096) {
        int m = i >> 12, j = i & 4095;
        const float4* srcp = (m == 0) ? wq : (m == 1) ? wp : wv;
        float4 v = srcp[j];
        __half2 h0 = __floats2half2_rn(v.x, v.y);
        __half2 h1 = __floats2half2_rn(v.z, v.w);
        uint2 pk;
        pk.x = *(unsigned*)&h0;
        pk.y = *(unsigned*)&h1;
        ((uint2*)g_wh)[i] = pk;
    }
}

// ---------------------------------------------------------------------------
// Tensor-core K/Q/V projection via WMMA: C = h @ W (fp16 in, fp32 acc).
// BM=64, BN=64. grid = (ceil(NN/64), 6): blockIdx.y = matrix*2 + n_half.
// 256 threads = 8 warps: warp w -> m-tile (w&3), n-pair (w>>2).
// Smem: A[64][136] + B[128][72] = 35840 B; fp32 staging reuses same region.
// ---------------------------------------------------------------------------
__global__ __launch_bounds__(256)
void kqv_gemm_wmma() {
    __shared__ __align__(16) char smem[35840];
    __half* As = (__half*)smem;             // [64][136]
    __half* Bs = (__half*)(smem + 17408);   // [128][72]
    float*  Cs = (float*)smem;              // [64][68] staging (after sync)

    const int mat = blockIdx.y >> 1;
    const int n0  = (blockIdx.y & 1) * 64;
    const __half* w = g_wh + mat * 128 * 128;
    __half* outp = (mat == 0) ? g_K : (mat == 1) ? g_Q : g_V;
    const int m0  = blockIdx.x * 64;
    const int tid = threadIdx.x;

    // Load A tile: 64 rows x 16 8-half chunks = 1024 chunks, 4 per thread
#pragma unroll
    for (int t = 0; t < 4; t++) {
        int ci = tid + t * 256;
        int row = ci >> 4, ch = ci & 15;
        uint4 v = make_uint4(0u, 0u, 0u, 0u);
        int gr = m0 + row;
        if (gr < NN) v = *(const uint4*)&g_hh[gr * 128 + ch * 8];
        *(uint4*)&As[row * 136 + ch * 8] = v;
    }
    // Load B tile: 128 rows x 8 chunks = 1024 chunks, 4 per thread
#pragma unroll
    for (int t = 0; t < 4; t++) {
        int ci = tid + t * 256;
        int row = ci >> 3, ch = ci & 7;
        *(uint4*)&Bs[row * 72 + ch * 8] =
            *(const uint4*)&w[row * 128 + n0 + ch * 8];
    }
    __syncthreads();

    const int wid   = tid >> 5;
    const int mt    = wid & 3;    // m-tile 0..3 (16 rows each)
    const int npair = wid >> 2;   // 0..1 (32 cols each)

    wmma::fragment<wmma::accumulator, 16, 16, 16, float> c[2];
    wmma::fill_fragment(c[0], 0.0f);
    wmma::fill_fragment(c[1], 0.0f);

#pragma unroll
    for (int k = 0; k < 8; k++) {
        wmma::fragment<wmma::matrix_a, 16, 16, 16, __half, wmma::row_major> a;
        wmma::load_matrix_sync(a, As + (mt * 16) * 136 + k * 16, 136);
#pragma unroll
        for (int j = 0; j < 2; j++) {
            wmma::fragment<wmma::matrix_b, 16, 16, 16, __half, wmma::row_major> b;
            wmma::load_matrix_sync(b, Bs + (k * 16) * 72 + npair * 32 + j * 16, 72);
            wmma::mma_sync(c[j], a, b, c[j]);
        }
    }
    __syncthreads();   // everyone done reading As/Bs before staging overwrites

#pragma unroll
    for (int j = 0; j < 2; j++)
        wmma::store_matrix_sync(Cs + (mt * 16) * 68 + npair * 32 + j * 16,
                                c[j], 68, wmma::mem_row_major);
    __syncthreads();

    // Convert fp32 staging -> fp16 output, coalesced: 64x64 = 2048 half2
#pragma unroll
    for (int t = 0; t < 8; t++) {
        int i = tid + t * 256;          // 0..2047
        int row = i >> 5, cp = i & 31;  // cp: half2 column-pair index
        int gr = m0 + row;
        if (gr < NN) {
            float2 f = *(float2*)&Cs[row * 68 + cp * 2];
            __half2 hv = __floats2half2_rn(f.x, f.y);
            *(unsigned*)&outp[gr * 128 + n0 + cp * 2] = *(unsigned*)&hv;
        }
    }
}

// ---------------------------------------------------------------------------
// Counting sort by dst: histogram -> 2-level exclusive scan -> scatter
// ---------------------------------------------------------------------------
__global__ void hist_kernel(const int* __restrict__ dst, int E) {
    int e = blockIdx.x * blockDim.x + threadIdx.x;
    if (e < E) atomicAdd(&g_count[dst[e]], 1);
}

__global__ void scan1_kernel() {
    __shared__ int sh[256];
    int i = blockIdx.x * 256 + threadIdx.x;
    int v = (i < NN) ? g_count[i] : 0;
    sh[threadIdx.x] = v;
    __syncthreads();
#pragma unroll
    for (int off = 1; off < 256; off <<= 1) {
        int t = (threadIdx.x >= off) ? sh[threadIdx.x - off] : 0;
        __syncthreads();
        sh[threadIdx.x] += t;
        __syncthreads();
    }
    if (i < NN) g_rowstart[i] = sh[threadIdx.x] - v;
    if (threadIdx.x == 255) g_bsum[blockIdx.x] = sh[255];
}

__global__ void scan2_kernel() {
    __shared__ int sh[256];
    int v = (threadIdx.x < SCAN_BLOCKS) ? g_bsum[threadIdx.x] : 0;
    sh[threadIdx.x] = v;
    __syncthreads();
#pragma unroll
    for (int off = 1; off < 256; off <<= 1) {
        int t = (threadIdx.x >= off) ? sh[threadIdx.x - off] : 0;
        __syncthreads();
        sh[threadIdx.x] += t;
        __syncthreads();
    }
    if (threadIdx.x < SCAN_BLOCKS) g_bsum[threadIdx.x] = sh[threadIdx.x] - v;
}

__global__ void scan3_kernel(int E) {
    int i = blockIdx.x * 256 + threadIdx.x;
    if (i < NN) {
        int r = g_rowstart[i] + g_bsum[blockIdx.x];
        g_rowstart[i] = r;
        g_cursor[i]   = r;
    }
    if (i == 0) g_rowstart[NN] = E;
}

__global__ void scatter_kernel(const int* __restrict__ src,
                               const int* __restrict__ dst, int E) {
    int e = blockIdx.x * blockDim.x + threadIdx.x;
    if (e < E) {
        int pos = atomicAdd(&g_cursor[dst[e]], 1);
        g_sorted_src[pos] = src[e];
    }
}

// ---------------------------------------------------------------------------
// Node kernel: one warp per dst node, fused score+aggregate+finalize.
// lane t: head = t>>2, channels [4t, 4t+4).
// ---------------------------------------------------------------------------
__global__ __launch_bounds__(256)
void node_kernel(float* __restrict__ out) {
    const int lane = threadIdx.x & 31;
    const int d    = (blockIdx.x * blockDim.x + threadIdx.x) >> 5;
    if (d >= NN) return;

    const uint2* __restrict__ K2 = (const uint2*)g_K;
    const uint2* __restrict__ Q2 = (const uint2*)g_Q;
    const uint2* __restrict__ V2 = (const uint2*)g_V;

    uint2 qr = Q2[d * 32 + lane];
    float2 q0 = __half22float2(*(__half2*)&qr.x);
    float2 q1 = __half22float2(*(__half2*)&qr.y);

    const int beg = g_rowstart[d];
    const int end = g_rowstart[d + 1];

    float a0 = 0.f, a1 = 0.f, a2 = 0.f, a3 = 0.f, z = 0.f;

    int s = (beg < end) ? g_sorted_src[beg] : 0;
    for (int i = beg; i < end; i++) {
        int s_next = (i + 1 < end) ? g_sorted_src[i + 1] : 0;

        uint2 kr = K2[s * 32 + lane];
        uint2 vr = V2[s * 32 + lane];

        float2 k0 = __half22float2(*(__half2*)&kr.x);
        float2 k1 = __half22float2(*(__half2*)&kr.y);
        float ps = k0.x * q0.x + k0.y * q0.y + k1.x * q1.x + k1.y * q1.y;
        ps += __shfl_xor_sync(0xFFFFFFFFu, ps, 1);
        ps += __shfl_xor_sync(0xFFFFFFFFu, ps, 2);
        float sc = __expf(fminf(fmaxf(ps * 0.25f, -5.f), 5.f));

        float2 v0 = __half22float2(*(__half2*)&vr.x);
        float2 v1 = __half22float2(*(__half2*)&vr.y);
        a0 = fmaf(v0.x, sc, a0);
        a1 = fmaf(v0.y, sc, a1);
        a2 = fmaf(v1.x, sc, a2);
        a3 = fmaf(v1.y, sc, a3);
        z += sc;

        s = s_next;
    }

    float zz = (z == 0.f) ? 0.001f : z;
    float inv = 1.0f / zz;
    float4 r = make_float4(a0 * inv, a1 * inv, a2 * inv, a3 * inv);
    *(float4*)&out[d * 128 + lane * 4] = r;
}

extern "C" void kernel_launch(void* const* d_in, const int* in_sizes, int n_in,
                              void* d_out, int out_size) {
    const float* h   = (const float*)d_in[0];
    const int*   src = (const int*)d_in[1];
    const int*   dst = (const int*)d_in[2];
    const float* p   = (const float*)d_in[3];
    const float* q   = (const float*)d_in[4];
    const float* wv  = (const float*)d_in[5];
    float* out = (float*)d_out;
    const int E = in_sizes[1];
    const int eg = (E + 255) / 256;

    init_kernel<<<SCAN_BLOCKS, 256>>>();
    convh_kernel<<<(NN * 32 + 255) / 256, 256>>>((const float4*)h);
    convw_kernel<<<48, 256>>>((const float4*)q, (const float4*)p,
                              (const float4*)wv);

    dim3 ggrid((NN + 63) / 64, 6);
    kqv_gemm_wmma<<<ggrid, 256>>>();

    hist_kernel<<<eg, 256>>>(dst, E);
    scan1_kernel<<<SCAN_BLOCKS, 256>>>();
    scan2_kernel<<<1, 256>>>();
    scan3_kernel<<<SCAN_BLOCKS, 256>>>(E);
    scatter_kernel<<<eg, 256>>>(src, dst, E);

    node_kernel<<<(NN * 32 + 255) / 256, 256>>>(out);
}

// round 8
// speedup vs baseline: 3.3058x; 1.1072x over previous
#include <cuda_runtime.h>
#include <cuda_fp16.h>
#include <cuda_bf16.h>
#include <mma.h>
#include <cstdint>

using namespace nvcuda;

#define NN    50000
#define EMAX  1700000
#define HEADS 8

// Scratch (no cudaMalloc allowed)
__device__ __half g_KV[NN * 256];          // per node: 128 K halves | 128 V halves
__device__ __half g_Q[NN * 128];
__device__ __half g_wh[3 * 128 * 128];     // q, p, Wv in fp16
__device__ int    g_count[NN];
__device__ int    g_rowstart[NN + 1];
__device__ int    g_cursor[NN];
__device__ int    g_bsum[256];
__device__ int    g_sorted_src[EMAX];

#define SCAN_BLOCKS 196   // 196*256 = 50176 >= NN

// ---------------------------------------------------------------------------
__global__ void init_kernel() {
    int i = blockIdx.x * blockDim.x + threadIdx.x;
    if (i < NN) g_count[i] = 0;
}

// fp32 -> fp16 weights (tiny: 3*128*128)
__global__ void convw_kernel(const float4* __restrict__ wq,
                             const float4* __restrict__ wp,
                             const float4* __restrict__ wv) {
    int i = blockIdx.x * blockDim.x + threadIdx.x;   // 3*4096 float4s
    if (i < 3 * 4096) {
        int m = i >> 12, j = i & 4095;
        const float4* srcp = (m == 0) ? wq : (m == 1) ? wp : wv;
        float4 v = srcp[j];
        __half2 h0 = __floats2half2_rn(v.x, v.y);
        __half2 h1 = __floats2half2_rn(v.z, v.w);
        uint2 pk;
        pk.x = *(unsigned*)&h0;
        pk.y = *(unsigned*)&h1;
        ((uint2*)g_wh)[i] = pk;
    }
}

// ---------------------------------------------------------------------------
// Fused K/Q/V projection via WMMA. One block: 64-row tile x 64-col half,
// computing ALL 3 matrices (A loaded+converted once, B per matrix).
// grid = (ceil(NN/64), 2). 256 threads = 8 warps: mt = wid&3, npair = wid>>2.
// Smem: A[64][136]h (17408B) + B[128][72]h (18432B); C staging reuses B region.
// ---------------------------------------------------------------------------
__global__ __launch_bounds__(256)
void kqv_gemm_fused(const float* __restrict__ h) {
    __shared__ __align__(16) char smem[35840];
    __half* As = (__half*)smem;             // [64][136]
    __half* Bs = (__half*)(smem + 17408);   // [128][72]
    float*  Cs = (float*)(smem + 17408);    // [64][68] staging (17408B <= 18432B)

    const int m0  = blockIdx.x * 64;
    const int n0  = blockIdx.y * 64;
    const int tid = threadIdx.x;

    // Load A tile fp32 -> fp16 into smem: 64 rows x 32 float4 = 2048, 8/thread
#pragma unroll
    for (int t = 0; t < 8; t++) {
        int i = tid + t * 256;           // 0..2047
        int row = i >> 5, c4 = i & 31;
        int gr = m0 + row;
        float4 v = make_float4(0.f, 0.f, 0.f, 0.f);
        if (gr < NN) v = *(const float4*)&h[gr * 128 + c4 * 4];
        __half2 h0 = __floats2half2_rn(v.x, v.y);
        __half2 h1 = __floats2half2_rn(v.z, v.w);
        uint2 pk;
        pk.x = *(unsigned*)&h0;
        pk.y = *(unsigned*)&h1;
        *(uint2*)&As[row * 136 + c4 * 4] = pk;
    }

    const int wid   = tid >> 5;
    const int lane  = tid & 31; (void)lane;
    const int mt    = wid & 3;    // m-tile 0..3 (16 rows)
    const int npair = wid >> 2;   // 0..1 (32 cols)

    for (int mat = 0; mat < 3; mat++) {
        __syncthreads();   // prior epilogue done reading Cs (=Bs region)

        // Load B tile fp16: 128 rows x 8 chunks = 1024, 4/thread
        const __half* w = g_wh + mat * 128 * 128;
#pragma unroll
        for (int t = 0; t < 4; t++) {
            int ci = tid + t * 256;
            int row = ci >> 3, ch = ci & 7;
            *(uint4*)&Bs[row * 72 + ch * 8] =
                *(const uint4*)&w[row * 128 + n0 + ch * 8];
        }
        __syncthreads();

        wmma::fragment<wmma::accumulator, 16, 16, 16, float> c[2];
        wmma::fill_fragment(c[0], 0.0f);
        wmma::fill_fragment(c[1], 0.0f);

#pragma unroll
        for (int k = 0; k < 8; k++) {
            wmma::fragment<wmma::matrix_a, 16, 16, 16, __half, wmma::row_major> a;
            wmma::load_matrix_sync(a, As + (mt * 16) * 136 + k * 16, 136);
#pragma unroll
            for (int j = 0; j < 2; j++) {
                wmma::fragment<wmma::matrix_b, 16, 16, 16, __half, wmma::row_major> b;
                wmma::load_matrix_sync(b, Bs + (k * 16) * 72 + npair * 32 + j * 16, 72);
                wmma::mma_sync(c[j], a, b, c[j]);
            }
        }
        __syncthreads();   // all warps done reading Bs

#pragma unroll
        for (int j = 0; j < 2; j++)
            wmma::store_matrix_sync(Cs + (mt * 16) * 68 + npair * 32 + j * 16,
                                    c[j], 68, wmma::mem_row_major);
        __syncthreads();

        // Epilogue: fp32 staging -> fp16, coalesced. K/V interleave in g_KV.
        __half* outp;
        int rstride, coff;
        if (mat == 0)      { outp = g_KV; rstride = 256; coff = 0;   }  // K
        else if (mat == 1) { outp = g_Q;  rstride = 128; coff = 0;   }  // Q
        else               { outp = g_KV; rstride = 256; coff = 128; }  // V
#pragma unroll
        for (int t = 0; t < 8; t++) {
            int i = tid + t * 256;          // 0..2047
            int row = i >> 5, cp = i & 31;
            int gr = m0 + row;
            if (gr < NN) {
                float2 f = *(float2*)&Cs[row * 68 + cp * 2];
                __half2 hv = __floats2half2_rn(f.x, f.y);
                *(unsigned*)&outp[gr * rstride + coff + n0 + cp * 2] =
                    *(unsigned*)&hv;
            }
        }
    }
}

// ---------------------------------------------------------------------------
// Counting sort by dst: histogram -> 2-level exclusive scan -> scatter
// ---------------------------------------------------------------------------
__global__ void hist_kernel(const int* __restrict__ dst, int E) {
    int e = blockIdx.x * blockDim.x + threadIdx.x;
    if (e < E) atomicAdd(&g_count[dst[e]], 1);
}

__global__ void scan1_kernel() {
    __shared__ int sh[256];
    int i = blockIdx.x * 256 + threadIdx.x;
    int v = (i < NN) ? g_count[i] : 0;
    sh[threadIdx.x] = v;
    __syncthreads();
#pragma unroll
    for (int off = 1; off < 256; off <<= 1) {
        int t = (threadIdx.x >= off) ? sh[threadIdx.x - off] : 0;
        __syncthreads();
        sh[threadIdx.x] += t;
        __syncthreads();
    }
    if (i < NN) g_rowstart[i] = sh[threadIdx.x] - v;
    if (threadIdx.x == 255) g_bsum[blockIdx.x] = sh[255];
}

__global__ void scan2_kernel() {
    __shared__ int sh[256];
    int v = (threadIdx.x < SCAN_BLOCKS) ? g_bsum[threadIdx.x] : 0;
    sh[threadIdx.x] = v;
    __syncthreads();
#pragma unroll
    for (int off = 1; off < 256; off <<= 1) {
        int t = (threadIdx.x >= off) ? sh[threadIdx.x - off] : 0;
        __syncthreads();
        sh[threadIdx.x] += t;
        __syncthreads();
    }
    if (threadIdx.x < SCAN_BLOCKS) g_bsum[threadIdx.x] = sh[threadIdx.x] - v;
}

__global__ void scan3_kernel(int E) {
    int i = blockIdx.x * 256 + threadIdx.x;
    if (i < NN) {
        int r = g_rowstart[i] + g_bsum[blockIdx.x];
        g_rowstart[i] = r;
        g_cursor[i]   = r;
    }
    if (i == 0) g_rowstart[NN] = E;
}

__global__ void scatter_kernel(const int* __restrict__ src,
                               const int* __restrict__ dst, int E) {
    int e = blockIdx.x * blockDim.x + threadIdx.x;
    if (e < E) {
        int pos = atomicAdd(&g_cursor[dst[e]], 1);
        g_sorted_src[pos] = src[e];
    }
}

// ---------------------------------------------------------------------------
// Node kernel: one warp per dst node, fused score+aggregate+finalize.
// K/V interleaved: one 512B row per src node. lane t: head=t>>2, ch [4t,4t+4).
// ---------------------------------------------------------------------------
__global__ __launch_bounds__(256)
void node_kernel(float* __restrict__ out) {
    const int lane = threadIdx.x & 31;
    const int d    = (blockIdx.x * blockDim.x + threadIdx.x) >> 5;
    if (d >= NN) return;

    const uint2* __restrict__ KV2 = (const uint2*)g_KV;   // 64 uint2 per node
    const uint2* __restrict__ Q2  = (const uint2*)g_Q;

    uint2 qr = Q2[d * 32 + lane];
    float2 q0 = __half22float2(*(__half2*)&qr.x);
    float2 q1 = __half22float2(*(__half2*)&qr.y);

    const int beg = g_rowstart[d];
    const int end = g_rowstart[d + 1];

    float a0 = 0.f, a1 = 0.f, a2 = 0.f, a3 = 0.f, z = 0.f;

    int s = (beg < end) ? g_sorted_src[beg] : 0;
    for (int i = beg; i < end; i++) {
        int s_next = (i + 1 < end) ? g_sorted_src[i + 1] : 0;

        uint2 kr = KV2[s * 64 + lane];
        uint2 vr = KV2[s * 64 + 32 + lane];

        float2 k0 = __half22float2(*(__half2*)&kr.x);
        float2 k1 = __half22float2(*(__half2*)&kr.y);
        float ps = k0.x * q0.x + k0.y * q0.y + k1.x * q1.x + k1.y * q1.y;
        ps += __shfl_xor_sync(0xFFFFFFFFu, ps, 1);
        ps += __shfl_xor_sync(0xFFFFFFFFu, ps, 2);
        float sc = __expf(fminf(fmaxf(ps * 0.25f, -5.f), 5.f));

        float2 v0 = __half22float2(*(__half2*)&vr.x);
        float2 v1 = __half22float2(*(__half2*)&vr.y);
        a0 = fmaf(v0.x, sc, a0);
        a1 = fmaf(v0.y, sc, a1);
        a2 = fmaf(v1.x, sc, a2);
        a3 = fmaf(v1.y, sc, a3);
        z += sc;

        s = s_next;
    }

    float zz = (z == 0.f) ? 0.001f : z;
    float inv = 1.0f / zz;
    float4 r = make_float4(a0 * inv, a1 * inv, a2 * inv, a3 * inv);
    *(float4*)&out[d * 128 + lane * 4] = r;
}

// ---------------------------------------------------------------------------
static cudaStream_t g_s2;
static cudaEvent_t  g_evFork, g_evJoin;
static int          g_streams_ready = 0;

extern "C" void kernel_launch(void* const* d_in, const int* in_sizes, int n_in,
                              void* d_out, int out_size) {
    const float* h   = (const float*)d_in[0];
    const int*   src = (const int*)d_in[1];
    const int*   dst = (const int*)d_in[2];
    const float* p   = (const float*)d_in[3];
    const float* q   = (const float*)d_in[4];
    const float* wv  = (const float*)d_in[5];
    float* out = (float*)d_out;
    const int E = in_sizes[1];
    const int eg = (E + 255) / 256;

    if (!g_streams_ready) {
        cudaStreamCreateWithFlags(&g_s2, cudaStreamNonBlocking);
        cudaEventCreateWithFlags(&g_evFork, cudaEventDisableTiming);
        cudaEventCreateWithFlags(&g_evJoin, cudaEventDisableTiming);
        g_streams_ready = 1;
    }

    // Fork: sort chain on g_s2, projection chain on default stream.
    cudaEventRecord(g_evFork, 0);
    cudaStreamWaitEvent(g_s2, g_evFork, 0);

    init_kernel<<<SCAN_BLOCKS, 256, 0, g_s2>>>();
    hist_kernel<<<eg, 256, 0, g_s2>>>(dst, E);
    scan1_kernel<<<SCAN_BLOCKS, 256, 0, g_s2>>>();
    scan2_kernel<<<1, 256, 0, g_s2>>>();
    scan3_kernel<<<SCAN_BLOCKS, 256, 0, g_s2>>>(E);
    scatter_kernel<<<eg, 256, 0, g_s2>>>(src, dst, E);
    cudaEventRecord(g_evJoin, g_s2);

    convw_kernel<<<48, 256>>>((const float4*)q, (const float4*)p,
                              (const float4*)wv);
    dim3 ggrid((NN + 63) / 64, 2);
    kqv_gemm_fused<<<ggrid, 256>>>(h);

    // Join, then the consumer of both chains.
    cudaStreamWaitEvent(0, g_evJoin, 0);
    node_kernel<<<(NN * 32 + 255) / 256, 256>>>(out);
}

// round 9
// speedup vs baseline: 3.3291x; 1.0070x over previous
#include <cuda_runtime.h>
#include <cuda_fp16.h>
#include <cuda_bf16.h>
#include <mma.h>
#include <cstdint>

using namespace nvcuda;

#define NN    50000
#define EMAX  1700000
#define HEADS 8

// Scratch (no cudaMalloc allowed)
__device__ __half g_KV[NN * 256];          // per node: 128 K halves | 128 V halves
__device__ __half g_Q[NN * 128];
__device__ int    g_count[NN];             // zero at load; re-zeroed every call
__device__ int    g_rowstart[NN + 1];
__device__ int    g_cursor[NN];
__device__ unsigned long long g_scanstate[256];
__device__ int    g_sorted_src[EMAX];

#define SCAN_BLOCKS 196   // 196*256 = 50176 >= NN

// ---------------------------------------------------------------------------
// Fused K/Q/V projection via WMMA. One block: 64-row tile x 64-col half,
// computing ALL 3 matrices. A (fp32 h) converted once; B (fp32 weights)
// converted in-flight per matrix. grid = (ceil(NN/64), 2).
// 256 threads = 8 warps: mt = wid&3, npair = wid>>2.
// Smem: A[64][136]h (17408B) + B[128][72]h (18432B); C staging reuses B region.
// ---------------------------------------------------------------------------
__global__ __launch_bounds__(256)
void kqv_gemm_fused(const float* __restrict__ h,
                    const float* __restrict__ wq,
                    const float* __restrict__ wp,
                    const float* __restrict__ wv) {
    __shared__ __align__(16) char smem[35840];
    __half* As = (__half*)smem;             // [64][136]
    __half* Bs = (__half*)(smem + 17408);   // [128][72]
    float*  Cs = (float*)(smem + 17408);    // [64][68] staging

    const int m0  = blockIdx.x * 64;
    const int n0  = blockIdx.y * 64;
    const int tid = threadIdx.x;

    // Load A tile fp32 -> fp16: 64 rows x 32 float4 = 2048, 8/thread
#pragma unroll
    for (int t = 0; t < 8; t++) {
        int i = tid + t * 256;
        int row = i >> 5, c4 = i & 31;
        int gr = m0 + row;
        float4 v = make_float4(0.f, 0.f, 0.f, 0.f);
        if (gr < NN) v = *(const float4*)&h[gr * 128 + c4 * 4];
        __half2 h0 = __floats2half2_rn(v.x, v.y);
        __half2 h1 = __floats2half2_rn(v.z, v.w);
        uint2 pk;
        pk.x = *(unsigned*)&h0;
        pk.y = *(unsigned*)&h1;
        *(uint2*)&As[row * 136 + c4 * 4] = pk;
    }

    const int wid   = tid >> 5;
    const int mt    = wid & 3;    // m-tile 0..3 (16 rows)
    const int npair = wid >> 2;   // 0..1 (32 cols)

    for (int mat = 0; mat < 3; mat++) {
        __syncthreads();   // prior epilogue done with Cs (=Bs region)

        // Load B tile fp32 -> fp16: 128 rows x 16 float4 (64 cols) = 2048, 8/thread
        const float* w = (mat == 0) ? wq : (mat == 1) ? wp : wv;
#pragma unroll
        for (int t = 0; t < 8; t++) {
            int i = tid + t * 256;
            int row = i >> 4, c4 = i & 15;
            float4 v = *(const float4*)&w[row * 128 + n0 + c4 * 4];
            __half2 h0 = __floats2half2_rn(v.x, v.y);
            __half2 h1 = __floats2half2_rn(v.z, v.w);
            uint2 pk;
            pk.x = *(unsigned*)&h0;
            pk.y = *(unsigned*)&h1;
            *(uint2*)&Bs[row * 72 + c4 * 4] = pk;
        }
        __syncthreads();

        wmma::fragment<wmma::accumulator, 16, 16, 16, float> c[2];
        wmma::fill_fragment(c[0], 0.0f);
        wmma::fill_fragment(c[1], 0.0f);

#pragma unroll
        for (int k = 0; k < 8; k++) {
            wmma::fragment<wmma::matrix_a, 16, 16, 16, __half, wmma::row_major> a;
            wmma::load_matrix_sync(a, As + (mt * 16) * 136 + k * 16, 136);
#pragma unroll
            for (int j = 0; j < 2; j++) {
                wmma::fragment<wmma::matrix_b, 16, 16, 16, __half, wmma::row_major> b;
                wmma::load_matrix_sync(b, Bs + (k * 16) * 72 + npair * 32 + j * 16, 72);
                wmma::mma_sync(c[j], a, b, c[j]);
            }
        }
        __syncthreads();   // all warps done reading Bs

#pragma unroll
        for (int j = 0; j < 2; j++)
            wmma::store_matrix_sync(Cs + (mt * 16) * 68 + npair * 32 + j * 16,
                                    c[j], 68, wmma::mem_row_major);
        __syncthreads();

        // Epilogue: fp32 staging -> fp16, coalesced. K/V interleave in g_KV.
        __half* outp;
        int rstride, coff;
        if (mat == 0)      { outp = g_KV; rstride = 256; coff = 0;   }  // K
        else if (mat == 1) { outp = g_Q;  rstride = 128; coff = 0;   }  // Q
        else               { outp = g_KV; rstride = 256; coff = 128; }  // V
#pragma unroll
        for (int t = 0; t < 8; t++) {
            int i = tid + t * 256;
            int row = i >> 5, cp = i & 31;
            int gr = m0 + row;
            if (gr < NN) {
                float2 f = *(float2*)&Cs[row * 68 + cp * 2];
                __half2 hv = __floats2half2_rn(f.x, f.y);
                *(unsigned*)&outp[gr * rstride + coff + n0 + cp * 2] =
                    *(unsigned*)&hv;
            }
        }
    }
}

// ---------------------------------------------------------------------------
// Counting sort by dst.
// hist: per-edge atomic histogram. Block 0 also resets scan state.
// ---------------------------------------------------------------------------
__global__ void hist_kernel(const int* __restrict__ dst, int E) {
    if (blockIdx.x == 0 && threadIdx.x < 256) g_scanstate[threadIdx.x] = 0ULL;
    int e = blockIdx.x * blockDim.x + threadIdx.x;
    if (e < E) atomicAdd(&g_count[dst[e]], 1);
}

// Single-pass decoupled-lookback exclusive scan of g_count -> rowstart/cursor.
// Also re-zeroes g_count (keeps the every-call-leaves-zero invariant).
__global__ void scan_fused(int E) {
    __shared__ int sh[256];
    __shared__ int s_prefix;
    const int b = blockIdx.x;
    const int i = b * 256 + threadIdx.x;
    int v = (i < NN) ? g_count[i] : 0;
    sh[threadIdx.x] = v;
    __syncthreads();
#pragma unroll
    for (int off = 1; off < 256; off <<= 1) {
        int t = (threadIdx.x >= off) ? sh[threadIdx.x - off] : 0;
        __syncthreads();
        sh[threadIdx.x] += t;
        __syncthreads();
    }
    const int total = sh[255];

    if (threadIdx.x == 0) {
        unsigned long long st;
        if (b == 0)
            st = (2ULL << 32) | (unsigned)total;   // inclusive known
        else
            st = (1ULL << 32) | (unsigned)total;   // aggregate only
        atomicExch(&g_scanstate[b], st);

        int prefix = 0;
        if (b > 0) {
            int j = b - 1;
            while (true) {
                unsigned long long s = atomicAdd(&g_scanstate[j], 0ULL);
                unsigned flag = (unsigned)(s >> 32);
                if (flag == 2u) { prefix += (int)(unsigned)s; break; }
                if (flag == 1u) { prefix += (int)(unsigned)s; j--; }
            }
            atomicExch(&g_scanstate[b],
                       (2ULL << 32) | (unsigned)(prefix + total));
        }
        s_prefix = prefix;
    }
    __syncthreads();

    if (i < NN) {
        int r = s_prefix + sh[threadIdx.x] - v;   // exclusive
        g_rowstart[i] = r;
        g_cursor[i]   = r;
        g_count[i]    = 0;                        // reset for next call
    }
    if (i == 0) g_rowstart[NN] = E;
}

__global__ void scatter_kernel(const int* __restrict__ src,
                               const int* __restrict__ dst, int E) {
    int e = blockIdx.x * blockDim.x + threadIdx.x;
    if (e < E) {
        int pos = atomicAdd(&g_cursor[dst[e]], 1);
        g_sorted_src[pos] = src[e];
    }
}

// ---------------------------------------------------------------------------
// Node kernel: one warp per dst node, fused score+aggregate+finalize.
// blockDim=64 (2 warps) for finer load-balance granularity.
// K/V interleaved: one 512B row per src node. lane t: head=t>>2, ch [4t,4t+4).
// ---------------------------------------------------------------------------
__global__ __launch_bounds__(64)
void node_kernel(float* __restrict__ out) {
    const int lane = threadIdx.x & 31;
    const int d    = (blockIdx.x * blockDim.x + threadIdx.x) >> 5;
    if (d >= NN) return;

    const uint2* __restrict__ KV2 = (const uint2*)g_KV;   // 64 uint2 per node
    const uint2* __restrict__ Q2  = (const uint2*)g_Q;

    uint2 qr = Q2[d * 32 + lane];
    float2 q0 = __half22float2(*(__half2*)&qr.x);
    float2 q1 = __half22float2(*(__half2*)&qr.y);

    const int beg = g_rowstart[d];
    const int end = g_rowstart[d + 1];

    float a0 = 0.f, a1 = 0.f, a2 = 0.f, a3 = 0.f, z = 0.f;

    int s = (beg < end) ? g_sorted_src[beg] : 0;
    for (int i = beg; i < end; i++) {
        int s_next = (i + 1 < end) ? g_sorted_src[i + 1] : 0;

        uint2 kr = KV2[s * 64 + lane];
        uint2 vr = KV2[s * 64 + 32 + lane];

        float2 k0 = __half22float2(*(__half2*)&kr.x);
        float2 k1 = __half22float2(*(__half2*)&kr.y);
        float ps = k0.x * q0.x + k0.y * q0.y + k1.x * q1.x + k1.y * q1.y;
        ps += __shfl_xor_sync(0xFFFFFFFFu, ps, 1);
        ps += __shfl_xor_sync(0xFFFFFFFFu, ps, 2);
        float sc = __expf(fminf(fmaxf(ps * 0.25f, -5.f), 5.f));

        float2 v0 = __half22float2(*(__half2*)&vr.x);
        float2 v1 = __half22float2(*(__half2*)&vr.y);
        a0 = fmaf(v0.x, sc, a0);
        a1 = fmaf(v0.y, sc, a1);
        a2 = fmaf(v1.x, sc, a2);
        a3 = fmaf(v1.y, sc, a3);
        z += sc;

        s = s_next;
    }

    float zz = (z == 0.f) ? 0.001f : z;
    float inv = 1.0f / zz;
    float4 r = make_float4(a0 * inv, a1 * inv, a2 * inv, a3 * inv);
    *(float4*)&out[d * 128 + lane * 4] = r;
}

// ---------------------------------------------------------------------------
static cudaStream_t g_s2;
static cudaEvent_t  g_evFork, g_evJoin;
static int          g_streams_ready = 0;

extern "C" void kernel_launch(void* const* d_in, const int* in_sizes, int n_in,
                              void* d_out, int out_size) {
    const float* h   = (const float*)d_in[0];
    const int*   src = (const int*)d_in[1];
    const int*   dst = (const int*)d_in[2];
    const float* p   = (const float*)d_in[3];
    const float* q   = (const float*)d_in[4];
    const float* wv  = (const float*)d_in[5];
    float* out = (float*)d_out;
    const int E = in_sizes[1];
    const int eg = (E + 255) / 256;

    if (!g_streams_ready) {
        cudaStreamCreateWithFlags(&g_s2, cudaStreamNonBlocking);
        cudaEventCreateWithFlags(&g_evFork, cudaEventDisableTiming);
        cudaEventCreateWithFlags(&g_evJoin, cudaEventDisableTiming);
        g_streams_ready = 1;
    }

    // Fork: sort chain on g_s2, projection chain on default stream.
    cudaEventRecord(g_evFork, 0);
    cudaStreamWaitEvent(g_s2, g_evFork, 0);

    hist_kernel<<<eg, 256, 0, g_s2>>>(dst, E);
    scan_fused<<<SCAN_BLOCKS, 256, 0, g_s2>>>(E);
    scatter_kernel<<<eg, 256, 0, g_s2>>>(src, dst, E);
    cudaEventRecord(g_evJoin, g_s2);

    dim3 ggrid((NN + 63) / 64, 2);
    kqv_gemm_fused<<<ggrid, 256>>>(h, q, p, wv);

    // Join, then the consumer of both chains.
    cudaStreamWaitEvent(0, g_evJoin, 0);
    node_kernel<<<(NN * 32 + 63) / 64, 64>>>(out);
}

// round 12
// speedup vs baseline: 3.6236x; 1.0885x over previous
#include <cuda_runtime.h>
#include <cuda_fp16.h>
#include <cuda_bf16.h>
#include <mma.h>
#include <cstdint>

using namespace nvcuda;

#define NN    50000
#define EMAX  1700000
#define HEADS 8

// Scratch (no cudaMalloc allowed)
__device__ __half g_KV[NN * 256];          // per node: 128 K halves | 128 V halves
__device__ __half g_Q[NN * 128];
__device__ int    g_count[NN];             // zero at load; re-zeroed every call
__device__ int    g_rowstart[NN + 1];
__device__ int    g_cursor[NN];
__device__ unsigned long long g_scanstate[256];
__device__ int    g_sorted_src[EMAX];

#define SCAN_BLOCKS 196   // 196*256 = 50176 >= NN
#define GEMM_SMEM   52224 // 17408 (A) + 34816 (B / C-staging)

// ---------------------------------------------------------------------------
// Fused K/Q/V projection via WMMA. One block: 64 rows x FULL 128 cols,
// all 3 matrices. 8 warps in 2x4: warp_row = wid>>2, warp_col = wid&3,
// each warp a 32x32 tile (2x2 fragments).
// Dynamic smem: A[64][136]h (17408B) | B[128][136]h (34816B).
// C staged as [64][136] fp32 in the B region (exactly 34816B).
// ---------------------------------------------------------------------------
__global__ __launch_bounds__(256)
void kqv_gemm_fused(const float* __restrict__ h,
                    const float* __restrict__ wq,
                    const float* __restrict__ wp,
                    const float* __restrict__ wv) {
    extern __shared__ __align__(16) char smem[];
    __half* As = (__half*)smem;             // [64][136]
    __half* Bs = (__half*)(smem + 17408);   // [128][136]
    float*  Cs = (float*)(smem + 17408);    // [64][136] staging

    const int m0  = blockIdx.x * 64;
    const int tid = threadIdx.x;

    // Load A tile fp32 -> fp16: 64 rows x 32 float4 = 2048, 8/thread
#pragma unroll
    for (int t = 0; t < 8; t++) {
        int i = tid + t * 256;
        int row = i >> 5, c4 = i & 31;
        int gr = m0 + row;
        float4 v = make_float4(0.f, 0.f, 0.f, 0.f);
        if (gr < NN) v = *(const float4*)&h[gr * 128 + c4 * 4];
        __half2 h0 = __floats2half2_rn(v.x, v.y);
        __half2 h1 = __floats2half2_rn(v.z, v.w);
        uint2 pk;
        pk.x = *(unsigned*)&h0;
        pk.y = *(unsigned*)&h1;
        *(uint2*)&As[row * 136 + c4 * 4] = pk;
    }

    const int wid      = tid >> 5;
    const int warp_row = wid >> 2;   // 0..1 (32 rows each)
    const int warp_col = wid & 3;    // 0..3 (32 cols each)

    for (int mat = 0; mat < 3; mat++) {
        __syncthreads();   // prior epilogue done with Cs (=Bs region)

        // Load B (mat) fp32 -> fp16: 128 rows x 32 float4 = 4096, 16/thread
        const float* w = (mat == 0) ? wq : (mat == 1) ? wp : wv;
#pragma unroll
        for (int t = 0; t < 16; t++) {
            int i = tid + t * 256;
            int row = i >> 5, c4 = i & 31;
            float4 v = *(const float4*)&w[row * 128 + c4 * 4];
            __half2 h0 = __floats2half2_rn(v.x, v.y);
            __half2 h1 = __floats2half2_rn(v.z, v.w);
            uint2 pk;
            pk.x = *(unsigned*)&h0;
            pk.y = *(unsigned*)&h1;
            *(uint2*)&Bs[row * 136 + c4 * 4] = pk;
        }
        __syncthreads();

        wmma::fragment<wmma::accumulator, 16, 16, 16, float> c[2][2];
#pragma unroll
        for (int i = 0; i < 2; i++)
#pragma unroll
            for (int j = 0; j < 2; j++) wmma::fill_fragment(c[i][j], 0.0f);

#pragma unroll
        for (int k = 0; k < 8; k++) {
            wmma::fragment<wmma::matrix_a, 16, 16, 16, __half, wmma::row_major> a[2];
            wmma::fragment<wmma::matrix_b, 16, 16, 16, __half, wmma::row_major> b[2];
#pragma unroll
            for (int i = 0; i < 2; i++)
                wmma::load_matrix_sync(a[i],
                    As + (warp_row * 32 + i * 16) * 136 + k * 16, 136);
#pragma unroll
            for (int j = 0; j < 2; j++)
                wmma::load_matrix_sync(b[j],
                    Bs + (k * 16) * 136 + warp_col * 32 + j * 16, 136);
#pragma unroll
            for (int i = 0; i < 2; i++)
#pragma unroll
                for (int j = 0; j < 2; j++)
                    wmma::mma_sync(c[i][j], a[i], b[j], c[i][j]);
        }
        __syncthreads();   // all warps done reading Bs

#pragma unroll
        for (int i = 0; i < 2; i++)
#pragma unroll
            for (int j = 0; j < 2; j++)
                wmma::store_matrix_sync(
                    Cs + (warp_row * 32 + i * 16) * 136 + warp_col * 32 + j * 16,
                    c[i][j], 136, wmma::mem_row_major);
        __syncthreads();

        // Epilogue: fp32 staging -> fp16, coalesced. K/V interleave in g_KV.
        __half* outp;
        int rstride, coff;
        if (mat == 0)      { outp = g_KV; rstride = 256; coff = 0;   }  // K
        else if (mat == 1) { outp = g_Q;  rstride = 128; coff = 0;   }  // Q
        else               { outp = g_KV; rstride = 256; coff = 128; }  // V
#pragma unroll
        for (int t = 0; t < 16; t++) {
            int i = tid + t * 256;          // 0..4095
            int row = i >> 6, cp = i & 63;  // 64 half2-pairs over 128 cols
            int gr = m0 + row;
            if (gr < NN) {
                float2 f = *(float2*)&Cs[row * 136 + cp * 2];
                __half2 hv = __floats2half2_rn(f.x, f.y);
                *(unsigned*)&outp[gr * rstride + coff + cp * 2] = *(unsigned*)&hv;
            }
        }
    }
}

// ---------------------------------------------------------------------------
// Counting sort by dst.
// ---------------------------------------------------------------------------
__global__ void hist_kernel(const int* __restrict__ dst, int E) {
    if (blockIdx.x == 0 && threadIdx.x < 256) g_scanstate[threadIdx.x] = 0ULL;
    int e = blockIdx.x * blockDim.x + threadIdx.x;
    if (e < E) atomicAdd(&g_count[dst[e]], 1);
}

// Single-pass decoupled-lookback exclusive scan; also re-zeroes g_count.
__global__ void scan_fused(int E) {
    __shared__ int sh[256];
    __shared__ int s_prefix;
    const int b = blockIdx.x;
    const int i = b * 256 + threadIdx.x;
    int v = (i < NN) ? g_count[i] : 0;
    sh[threadIdx.x] = v;
    __syncthreads();
#pragma unroll
    for (int off = 1; off < 256; off <<= 1) {
        int t = (threadIdx.x >= off) ? sh[threadIdx.x - off] : 0;
        __syncthreads();
        sh[threadIdx.x] += t;
        __syncthreads();
    }
    const int total = sh[255];

    if (threadIdx.x == 0) {
        unsigned long long st;
        if (b == 0)
            st = (2ULL << 32) | (unsigned)total;   // inclusive known
        else
            st = (1ULL << 32) | (unsigned)total;   // aggregate only
        atomicExch(&g_scanstate[b], st);

        int prefix = 0;
        if (b > 0) {
            int j = b - 1;
            while (true) {
                unsigned long long s = atomicAdd(&g_scanstate[j], 0ULL);
                unsigned flag = (unsigned)(s >> 32);
                if (flag == 2u) { prefix += (int)(unsigned)s; break; }
                if (flag == 1u) { prefix += (int)(unsigned)s; j--; }
            }
            atomicExch(&g_scanstate[b],
                       (2ULL << 32) | (unsigned)(prefix + total));
        }
        s_prefix = prefix;
    }
    __syncthreads();

    if (i < NN) {
        int r = s_prefix + sh[threadIdx.x] - v;   // exclusive
        g_rowstart[i] = r;
        g_cursor[i]   = r;
        g_count[i]    = 0;                        // reset for next call
    }
    if (i == 0) g_rowstart[NN] = E;
}

__global__ void scatter_kernel(const int* __restrict__ src,
                               const int* __restrict__ dst, int E) {
    int e = blockIdx.x * blockDim.x + threadIdx.x;
    if (e < E) {
        int pos = atomicAdd(&g_cursor[dst[e]], 1);
        g_sorted_src[pos] = src[e];
    }
}

// ---------------------------------------------------------------------------
// Node kernel: one warp per dst node, 2-edge unroll (MLP 4 on KV gathers).
// K/V interleaved: one 512B row per src node. lane t: head=t>>2, ch [4t,4t+4).
// ---------------------------------------------------------------------------
__global__ __launch_bounds__(64)
void node_kernel(float* __restrict__ out) {
    const int lane = threadIdx.x & 31;
    const int d    = (blockIdx.x * blockDim.x + threadIdx.x) >> 5;
    if (d >= NN) return;

    const uint2* __restrict__ KV2 = (const uint2*)g_KV;   // 64 uint2 per node
    const uint2* __restrict__ Q2  = (const uint2*)g_Q;

    uint2 qr = Q2[d * 32 + lane];
    float2 q0 = __half22float2(*(__half2*)&qr.x);
    float2 q1 = __half22float2(*(__half2*)&qr.y);

    const int beg = g_rowstart[d];
    const int end = g_rowstart[d + 1];

    float a0 = 0.f, a1 = 0.f, a2 = 0.f, a3 = 0.f, z = 0.f;

    int i = beg;
    for (; i + 2 <= end; i += 2) {
        int s0 = g_sorted_src[i];
        int s1 = g_sorted_src[i + 1];

        uint2 kr0 = KV2[s0 * 64 + lane];
        uint2 vr0 = KV2[s0 * 64 + 32 + lane];
        uint2 kr1 = KV2[s1 * 64 + lane];
        uint2 vr1 = KV2[s1 * 64 + 32 + lane];

        float2 k00 = __half22float2(*(__half2*)&kr0.x);
        float2 k01 = __half22float2(*(__half2*)&kr0.y);
        float2 k10 = __half22float2(*(__half2*)&kr1.x);
        float2 k11 = __half22float2(*(__half2*)&kr1.y);

        float p0 = k00.x * q0.x + k00.y * q0.y + k01.x * q1.x + k01.y * q1.y;
        float p1 = k10.x * q0.x + k10.y * q0.y + k11.x * q1.x + k11.y * q1.y;
        p0 += __shfl_xor_sync(0xFFFFFFFFu, p0, 1);
        p1 += __shfl_xor_sync(0xFFFFFFFFu, p1, 1);
        p0 += __shfl_xor_sync(0xFFFFFFFFu, p0, 2);
        p1 += __shfl_xor_sync(0xFFFFFFFFu, p1, 2);
        float sc0 = __expf(fminf(fmaxf(p0 * 0.25f, -5.f), 5.f));
        float sc1 = __expf(fminf(fmaxf(p1 * 0.25f, -5.f), 5.f));

        float2 v00 = __half22float2(*(__half2*)&vr0.x);
        float2 v01 = __half22float2(*(__half2*)&vr0.y);
        float2 v10 = __half22float2(*(__half2*)&vr1.x);
        float2 v11 = __half22float2(*(__half2*)&vr1.y);

        a0 = fmaf(v00.x, sc0, a0); a1 = fmaf(v00.y, sc0, a1);
        a2 = fmaf(v01.x, sc0, a2); a3 = fmaf(v01.y, sc0, a3);
        a0 = fmaf(v10.x, sc1, a0); a1 = fmaf(v10.y, sc1, a1);
        a2 = fmaf(v11.x, sc1, a2); a3 = fmaf(v11.y, sc1, a3);
        z += sc0 + sc1;
    }
    if (i < end) {
        int s = g_sorted_src[i];
        uint2 kr = KV2[s * 64 + lane];
        uint2 vr = KV2[s * 64 + 32 + lane];
        float2 k0 = __half22float2(*(__half2*)&kr.x);
        float2 k1 = __half22float2(*(__half2*)&kr.y);
        float ps = k0.x * q0.x + k0.y * q0.y + k1.x * q1.x + k1.y * q1.y;
        ps += __shfl_xor_sync(0xFFFFFFFFu, ps, 1);
        ps += __shfl_xor_sync(0xFFFFFFFFu, ps, 2);
        float sc = __expf(fminf(fmaxf(ps * 0.25f, -5.f), 5.f));
        float2 v0 = __half22float2(*(__half2*)&vr.x);
        float2 v1 = __half22float2(*(__half2*)&vr.y);
        a0 = fmaf(v0.x, sc, a0); a1 = fmaf(v0.y, sc, a1);
        a2 = fmaf(v1.x, sc, a2); a3 = fmaf(v1.y, sc, a3);
        z += sc;
    }

    float zz = (z == 0.f) ? 0.001f : z;
    float inv = 1.0f / zz;
    float4 r = make_float4(a0 * inv, a1 * inv, a2 * inv, a3 * inv);
    *(float4*)&out[d * 128 + lane * 4] = r;
}

// ---------------------------------------------------------------------------
static cudaStream_t g_s2;
static cudaEvent_t  g_evFork, g_evJoin;
static int          g_streams_ready = 0;

extern "C" void kernel_launch(void* const* d_in, const int* in_sizes, int n_in,
                              void* d_out, int out_size) {
    const float* h   = (const float*)d_in[0];
    const int*   src = (const int*)d_in[1];
    const int*   dst = (const int*)d_in[2];
    const float* p   = (const float*)d_in[3];
    const float* q   = (const float*)d_in[4];
    const float* wv  = (const float*)d_in[5];
    float* out = (float*)d_out;
    const int E = in_sizes[1];
    const int eg = (E + 255) / 256;

    if (!g_streams_ready) {
        cudaStreamCreateWithFlags(&g_s2, cudaStreamNonBlocking);
        cudaEventCreateWithFlags(&g_evFork, cudaEventDisableTiming);
        cudaEventCreateWithFlags(&g_evJoin, cudaEventDisableTiming);
        cudaFuncSetAttribute(kqv_gemm_fused,
                             cudaFuncAttributeMaxDynamicSharedMemorySize,
                             GEMM_SMEM);
        g_streams_ready = 1;
    }

    // Fork: sort chain on g_s2, projection chain on default stream.
    cudaEventRecord(g_evFork, 0);
    cudaStreamWaitEvent(g_s2, g_evFork, 0);

    hist_kernel<<<eg, 256, 0, g_s2>>>(dst, E);
    scan_fused<<<SCAN_BLOCKS, 256, 0, g_s2>>>(E);
    scatter_kernel<<<eg, 256, 0, g_s2>>>(src, dst, E);
    cudaEventRecord(g_evJoin, g_s2);

    kqv_gemm_fused<<<(NN + 63) / 64, 256, GEMM_SMEM>>>(h, q, p, wv);

    // Join, then the consumer of both chains.
    cudaStreamWaitEvent(0, g_evJoin, 0);
    node_kernel<<<(NN * 32 + 63) / 64, 64>>>(out);
}